// round 6
// baseline (speedup 1.0000x reference)
#include <cuda_runtime.h>
#include <cuda_fp16.h>

#define B_  16
#define Q_  1000
#define N_  16
#define C_  256
#define H_  100
#define W_  100
#define HW_ 10000
#define NH_ 8
#define D_  32
#define TQ  4          // queries per fused block
#define MP  20         // queries per proj block
#define AP2 264        // A_sm row pitch in halves (528B rows, 16B-aligned)

// ---- fused kernel smem offsets (bytes) ----
#define OFF_A    0
#define SZ_A     (TQ*N_*AP2*2)          // 33792 half A[64][264]
#define OFF_TM   (OFF_A + SZ_A)         // 33792 half tm[4][8][256] (t then m)
#define SZ_TM    (TQ*NH_*C_*2)          // 16384
#define OFF_SC   (OFF_TM + SZ_TM)       // 50176 float sc[4][8][16]
#define SZ_SC    (TQ*NH_*N_*4)          // 2048
#define OFF_AT   (OFF_SC + SZ_SC)       // 52224 float at[4][16][8]
#define SZ_AT    (TQ*N_*NH_*4)          // 2048
#define OFF_U    (OFF_AT + SZ_AT)       // 54272 float u[32]
#define SZ_U     (TQ*NH_*4)             // 128
#define OFF_WT   (OFF_U + SZ_U)         // 54400 float4 wt[64]
#define SZ_WT    (TQ*N_*16)             // 1024
#define OFF_OY   (OFF_WT + SZ_WT)       // 55424 int2 oy[64]
#define SZ_OY    (TQ*N_*8)              // 512
#define OFF_OX   (OFF_OY + SZ_OY)       // 55936 ushort2 ox[64]
#define SZ_OX    (TQ*N_*4)              // 256
#define SMEM_BYTES (OFF_OX + SZ_OX)     // 56192 -> 3 blocks/SM

#define PROJ_SMEM (MP*C_*4*2)           // 40960

// device scratch
__device__ __half g_xt[B_ * HW_ * C_];        // channels-last fp16 x
__device__ float  g_wqT[C_ * C_];             // wq transposed [k][c]
__device__ float  g_wvT[C_ * C_];             // wv transposed [k][c]
__device__ __half g_t[(size_t)B_ * Q_ * NH_ * C_];   // t[b,q,h,k]
__device__ float  g_u[(size_t)B_ * Q_ * NH_];        // u[b,q,h]

// ---------------------------------------------------------------------------
// Prologue A: transpose wq, wv [c][k] -> [k][c]
// ---------------------------------------------------------------------------
__global__ void transpose_w_kernel(const float* __restrict__ wq,
                                   const float* __restrict__ wv) {
    __shared__ float tile[32][33];
    const float* src = blockIdx.z == 0 ? wq : wv;
    float* dst = blockIdx.z == 0 ? g_wqT : g_wvT;
    int c0 = blockIdx.x * 32;
    int k0 = blockIdx.y * 32;
    int tx = threadIdx.x, ty = threadIdx.y;   // 32x8
    #pragma unroll
    for (int dy = 0; dy < 32; dy += 8)
        tile[ty + dy][tx] = src[(size_t)(c0 + ty + dy) * C_ + k0 + tx];
    __syncthreads();
    #pragma unroll
    for (int dy = 0; dy < 32; dy += 8)
        dst[(size_t)(k0 + ty + dy) * C_ + c0 + tx] = tile[tx][ty + dy];
}

// ---------------------------------------------------------------------------
// Prologue B: transpose x [B,C,HW] -> g_xt [B,HW,C] (fp16)
// ---------------------------------------------------------------------------
__global__ void transpose_x_kernel(const float* __restrict__ x) {
    __shared__ float tile[32][33];
    int b  = blockIdx.z;
    int p0 = blockIdx.x * 32;   // HW
    int c0 = blockIdx.y * 32;   // C
    int tx = threadIdx.x, ty = threadIdx.y;   // 32x8
    #pragma unroll
    for (int dy = 0; dy < 32; dy += 8) {
        int c = c0 + ty + dy;
        int p = p0 + tx;
        float v = 0.f;
        if (p < HW_) v = x[(size_t)(b * C_ + c) * HW_ + p];
        tile[ty + dy][tx] = v;
    }
    __syncthreads();
    #pragma unroll
    for (int dy = 0; dy < 32; dy += 8) {
        int p = p0 + ty + dy;
        int c = c0 + tx;
        if (p < HW_)
            g_xt[(size_t)(b * HW_ + p) * C_ + c] = __float2half_rn(tile[tx][ty + dy]);
    }
}

// ---------------------------------------------------------------------------
// Kernel P: projections (round-4 proven layout, fp32 scalar math).
// qp = q@wqT+bq, t[h] = qp_head@wk_head (fp16 out), u = qp_head.bk_head.
// 256 threads, MP=20 queries/block.
// ---------------------------------------------------------------------------
__global__ __launch_bounds__(256)
void proj_kernel(const float* __restrict__ q,  const float* __restrict__ bq,
                 const float* __restrict__ wk, const float* __restrict__ bk) {
    extern __shared__ float psm[];
    float* qb = psm;                 // [MP][256]
    float* qp = psm + MP * C_;       // [MP][256]

    const int tid = threadIdx.x;
    const int b   = blockIdx.y;
    const int q0  = blockIdx.x * MP;

    for (int idx = tid; idx < MP * C_; idx += 256)
        qb[idx] = q[(size_t)(b * Q_ + q0 + idx / C_) * C_ + (idx % C_)];
    __syncthreads();

    // ---- qp phase: thread owns c; coalesced wqT reads; 4 FMA per LDS.128 ----
    {
        const int c = tid;
        float acc[MP];
        #pragma unroll
        for (int i = 0; i < MP; i++) acc[i] = 0.f;
        #pragma unroll 2
        for (int k4 = 0; k4 < C_ / 4; k4++) {
            const float* wp = g_wqT + (size_t)(k4 * 4) * C_ + c;
            float w0 = __ldg(wp);
            float w1 = __ldg(wp + C_);
            float w2 = __ldg(wp + 2 * C_);
            float w3 = __ldg(wp + 3 * C_);
            #pragma unroll
            for (int i = 0; i < MP; i++) {
                float4 qv = *(const float4*)(qb + i * C_ + k4 * 4);
                acc[i] += qv.x * w0 + qv.y * w1 + qv.z * w2 + qv.w * w3;
            }
        }
        float bb = __ldg(bq + c);
        #pragma unroll
        for (int i = 0; i < MP; i++) qp[i * C_ + c] = acc[i] + bb;
    }
    __syncthreads();

    // ---- t phase: thread owns k; coalesced wk reads ----
    {
        const int k = tid;
        for (int h = 0; h < NH_; h++) {
            float acc[MP];
            #pragma unroll
            for (int i = 0; i < MP; i++) acc[i] = 0.f;
            #pragma unroll 2
            for (int d4 = 0; d4 < D_ / 4; d4++) {
                const float* wp = wk + (size_t)(h * D_ + d4 * 4) * C_ + k;
                float w0 = __ldg(wp);
                float w1 = __ldg(wp + C_);
                float w2 = __ldg(wp + 2 * C_);
                float w3 = __ldg(wp + 3 * C_);
                #pragma unroll
                for (int i = 0; i < MP; i++) {
                    float4 qv = *(const float4*)(qp + i * C_ + h * D_ + d4 * 4);
                    acc[i] += qv.x * w0 + qv.y * w1 + qv.z * w2 + qv.w * w3;
                }
            }
            #pragma unroll
            for (int i = 0; i < MP; i++)
                g_t[((size_t)(b * Q_ + q0 + i) * NH_ + h) * C_ + k] =
                    __float2half_rn(acc[i]);
        }
    }

    // ---- u phase ----
    if (tid < MP * NH_) {
        int i = tid / NH_, h = tid % NH_;
        float s = 0.f;
        #pragma unroll
        for (int dd = 0; dd < D_; dd++)
            s += qp[i * C_ + h * D_ + dd] * __ldg(bk + h * D_ + dd);
        g_u[(size_t)(b * Q_ + q0 + i) * NH_ + h] = s;
    }
}

// ---------------------------------------------------------------------------
// Kernel F: fused gather + attention + output proj.
// TQ=4 queries/block, 512 threads, 3 blocks/SM (48 warps).
// ---------------------------------------------------------------------------
__global__ __launch_bounds__(512, 3)
void deform_attn_kernel(const float* __restrict__ ref,
                        const float* __restrict__ bv,
                        float* __restrict__ out) {
    extern __shared__ char smc[];
    __half*  A_sm  = (__half*)(smc + OFF_A);
    __half*  tm_sm = (__half*)(smc + OFF_TM);
    float*   sc_sm = (float*)(smc + OFF_SC);
    float*   at_sm = (float*)(smc + OFF_AT);
    float*   u_sm  = (float*)(smc + OFF_U);
    float4*  wt_sm = (float4*)(smc + OFF_WT);
    int2*    oy_sm = (int2*)(smc + OFF_OY);
    ushort2* ox_sm = (ushort2*)(smc + OFF_OX);

    const int tid = threadIdx.x;
    const int b   = blockIdx.y;
    const int gq0 = blockIdx.x * TQ;

    // ---- phase 0: ref precompute (64 thr) + t/u load (all, coalesced) ----
    if (tid < TQ * N_) {
        int i  = tid >> 4, j = tid & 15;
        int rr = (gq0 + i) * N_ + j;
        int n  = rr / Q_;
        int qq = rr - n * Q_;
        float2 g = __ldg((const float2*)(ref + (size_t)((b * Q_ + qq) * N_ + n) * 2));
        float gx = ((g.x + 1.0f) * (float)W_ - 1.0f) * 0.5f;
        float gy = ((g.y + 1.0f) * (float)H_ - 1.0f) * 0.5f;
        float x0f = floorf(gx), y0f = floorf(gy);
        float fx = gx - x0f, fy = gy - y0f;
        int x0 = (int)x0f, y0 = (int)y0f;
        int x1 = x0 + 1,   y1 = y0 + 1;
        bool vx0 = (x0 >= 0) & (x0 < W_);
        bool vx1 = (x1 >= 0) & (x1 < W_);
        bool vy0 = (y0 >= 0) & (y0 < H_);
        bool vy1 = (y1 >= 0) & (y1 < H_);
        float4 w;
        w.x = (vx0 && vy0) ? (1.f - fx) * (1.f - fy) : 0.f;
        w.y = (vx1 && vy0) ? fx * (1.f - fy)         : 0.f;
        w.z = (vx0 && vy1) ? (1.f - fx) * fy         : 0.f;
        w.w = (vx1 && vy1) ? fx * fy                 : 0.f;
        int x0c = min(max(x0, 0), W_ - 1);
        int x1c = min(max(x1, 0), W_ - 1);
        int y0c = min(max(y0, 0), H_ - 1);
        int y1c = min(max(y1, 0), H_ - 1);
        wt_sm[tid] = w;
        oy_sm[tid] = make_int2(y0c * W_ * C_, y1c * W_ * C_);
        ox_sm[tid] = make_ushort2((unsigned short)(x0c * C_),
                                  (unsigned short)(x1c * C_));
    }
    // t load: TQ*NH_*C_ = 8192 halves = 1024 uint4
    {
        const uint4* ts = (const uint4*)(g_t + (size_t)(b * Q_ + gq0) * NH_ * C_);
        uint4* td = (uint4*)tm_sm;
        td[tid] = __ldg(ts + tid);
        td[tid + 512] = __ldg(ts + tid + 512);
    }
    if (tid < TQ * NH_)
        u_sm[tid] = __ldg(g_u + (size_t)(b * Q_ + gq0) * NH_ + tid);
    __syncthreads();

    // ---- gather: thread owns k-pair; 16 rows each; full-line LDG.32 taps ----
    {
        const int k2 = tid & 127;           // half2 index
        const int rg = tid >> 7;            // 0..3
        const __half* xb = g_xt + (size_t)b * HW_ * C_;
        #pragma unroll 4
        for (int row = rg; row < TQ * N_; row += 4) {
            float4  w  = wt_sm[row];
            int2    oy = oy_sm[row];
            ushort2 ox = ox_sm[row];
            float2 v00 = __half22float2(__ldg((const __half2*)(xb + oy.x + ox.x) + k2));
            float2 v01 = __half22float2(__ldg((const __half2*)(xb + oy.x + ox.y) + k2));
            float2 v10 = __half22float2(__ldg((const __half2*)(xb + oy.y + ox.x) + k2));
            float2 v11 = __half22float2(__ldg((const __half2*)(xb + oy.y + ox.y) + k2));
            float rx = w.x * v00.x + w.y * v01.x + w.z * v10.x + w.w * v11.x;
            float ry = w.x * v00.y + w.y * v01.y + w.z * v10.y + w.w * v11.y;
            *(__half2*)(A_sm + row * AP2 + 2 * k2) = __floats2half2_rn(rx, ry);
        }
    }
    __syncthreads();

    // ---- scores: 512 threads = one (i,j,h) each; uint4 (8-half) loads ----
    {
        const int i = tid >> 7;
        const int j = (tid >> 3) & 15;
        const int h = tid & 7;
        const uint4* arow = (const uint4*)(A_sm + (i * N_ + j) * AP2);
        const uint4* trow = (const uint4*)(tm_sm + (i * NH_ + h) * C_);
        float acc = 0.f;
        #pragma unroll 4
        for (int k8 = 0; k8 < C_ / 8; k8++) {
            uint4 av = arow[k8];
            uint4 tv = trow[k8];
            const __half2* ah = (const __half2*)&av;
            const __half2* th = (const __half2*)&tv;
            #pragma unroll
            for (int p = 0; p < 4; p++) {
                float2 af = __half22float2(ah[p]);
                float2 tf = __half22float2(th[p]);
                acc += af.x * tf.x + af.y * tf.y;
            }
        }
        const float scale = 0.17677669529663687f; // 1/sqrt(32)
        sc_sm[(i * NH_ + h) * N_ + j] = (acc + u_sm[i * NH_ + h]) * scale;
    }
    __syncthreads();

    // ---- softmax over j per (i,h): 32 threads; attn transposed fp32 ----
    if (tid < TQ * NH_) {
        int i = tid >> 3, h = tid & 7;
        float s[N_];
        float mx = -1e30f;
        #pragma unroll
        for (int j = 0; j < N_; j++) {
            s[j] = sc_sm[(i * NH_ + h) * N_ + j];
            mx = fmaxf(mx, s[j]);
        }
        float sum = 0.f;
        #pragma unroll
        for (int j = 0; j < N_; j++) { s[j] = expf(s[j] - mx); sum += s[j]; }
        float inv = 1.f / sum;
        #pragma unroll
        for (int j = 0; j < N_; j++)
            at_sm[(i * N_ + j) * NH_ + h] = s[j] * inv;
    }
    __syncthreads();

    // ---- m[i][h][k] = sum_j attn*A : (k, i-group); overwrite tm ----
    {
        const int k = tid & 255;
        const int g = tid >> 8;
        #pragma unroll
        for (int ii = 0; ii < TQ / 2; ii++) {
            int i = g * (TQ / 2) + ii;
            float acc[NH_];
            #pragma unroll
            for (int h = 0; h < NH_; h++) acc[h] = 0.f;
            #pragma unroll
            for (int j = 0; j < N_; j++) {
                float a = __half2float(A_sm[(i * N_ + j) * AP2 + k]);
                float4 p0 = *(const float4*)(at_sm + (i * N_ + j) * NH_);
                float4 p1 = *(const float4*)(at_sm + (i * N_ + j) * NH_ + 4);
                acc[0] += a * p0.x; acc[1] += a * p0.y;
                acc[2] += a * p0.z; acc[3] += a * p0.w;
                acc[4] += a * p1.x; acc[5] += a * p1.y;
                acc[6] += a * p1.z; acc[7] += a * p1.w;
            }
            #pragma unroll
            for (int h = 0; h < NH_; h++)
                tm_sm[(i * NH_ + h) * C_ + k] = __float2half_rn(acc[h]);
        }
    }
    __syncthreads();

    // ---- out[i][c] = sum_k m[i][h(c)][k]*wvT[k][c] + bv[c] : (c, i-group) ----
    {
        const int c = tid & 255;
        const int g = tid >> 8;
        const int h = c >> 5;
        float bb = __ldg(bv + c);
        float acc[TQ / 2];
        #pragma unroll
        for (int ii = 0; ii < TQ / 2; ii++) acc[ii] = bb;
        #pragma unroll 2
        for (int k4 = 0; k4 < C_ / 4; k4++) {
            const float* wp = g_wvT + (size_t)(k4 * 4) * C_ + c;
            float w0 = __ldg(wp);
            float w1 = __ldg(wp + C_);
            float w2 = __ldg(wp + 2 * C_);
            float w3 = __ldg(wp + 3 * C_);
            #pragma unroll
            for (int ii = 0; ii < TQ / 2; ii++) {
                int i = g * (TQ / 2) + ii;
                const __half2* mp =
                    (const __half2*)(tm_sm + (i * NH_ + h) * C_ + k4 * 4);
                float2 m01 = __half22float2(mp[0]);
                float2 m23 = __half22float2(mp[1]);
                acc[ii] += m01.x * w0 + m01.y * w1 + m23.x * w2 + m23.y * w3;
            }
        }
        #pragma unroll
        for (int ii = 0; ii < TQ / 2; ii++) {
            int i = g * (TQ / 2) + ii;
            out[(size_t)(b * Q_ + gq0 + i) * C_ + c] = acc[ii];
        }
    }
}

// ---------------------------------------------------------------------------
extern "C" void kernel_launch(void* const* d_in, const int* in_sizes, int n_in,
                              void* d_out, int out_size) {
    const float* x   = (const float*)d_in[0];
    const float* q   = (const float*)d_in[1];
    const float* ref = (const float*)d_in[2];
    const float* wq  = (const float*)d_in[3];
    const float* bq  = (const float*)d_in[4];
    const float* wk  = (const float*)d_in[5];
    const float* bk  = (const float*)d_in[6];
    const float* wv  = (const float*)d_in[7];
    const float* bv  = (const float*)d_in[8];
    float* out = (float*)d_out;

    (void)in_sizes; (void)n_in; (void)out_size;

    transpose_w_kernel<<<dim3(C_ / 32, C_ / 32, 2), dim3(32, 8)>>>(wq, wv);

    dim3 tg((HW_ + 31) / 32, C_ / 32, B_);
    transpose_x_kernel<<<tg, dim3(32, 8)>>>(x);

    cudaFuncSetAttribute(proj_kernel,
                         cudaFuncAttributeMaxDynamicSharedMemorySize, PROJ_SMEM);
    proj_kernel<<<dim3(Q_ / MP, B_), 256, PROJ_SMEM>>>(q, bq, wk, bk);

    cudaFuncSetAttribute(deform_attn_kernel,
                         cudaFuncAttributeMaxDynamicSharedMemorySize, SMEM_BYTES);
    deform_attn_kernel<<<dim3(Q_ / TQ, B_), 512, SMEM_BYTES>>>(ref, bv, out);
}

// round 7
// speedup vs baseline: 1.3779x; 1.3779x over previous
#include <cuda_runtime.h>
#include <cuda_fp16.h>

#define B_  16
#define Q_  1000
#define N_  16
#define C_  256
#define H_  100
#define W_  100
#define HW_ 10000
#define NH_ 8
#define D_  32
#define TQ  4          // queries per fused block
#define MP  20         // queries per proj block
#define MB  16         // queries per out block
#define AP2 264        // A_sm row pitch in halves

// ---- fused kernel smem offsets (bytes) ----
#define OFF_A    0
#define SZ_A     (TQ*N_*AP2*2)          // 33792 half A[64][264]
#define OFF_T    (OFF_A + SZ_A)         // 33792 half t[4][8][256]
#define SZ_T     (TQ*NH_*C_*2)          // 16384
#define OFF_PS   (OFF_T + SZ_T)         // 50176 float ps[4][512]
#define SZ_PS    (4*512*4)              // 8192
#define OFF_SC   (OFF_PS + SZ_PS)       // 58368 float sc[4][8][16]
#define SZ_SC    (TQ*NH_*N_*4)          // 2048
#define OFF_AT   (OFF_SC + SZ_SC)       // 60416 float at[4][16][8]
#define SZ_AT    (TQ*N_*NH_*4)          // 2048
#define OFF_U    (OFF_AT + SZ_AT)       // 62464 float u[32]
#define SZ_U     (TQ*NH_*4)             // 128
#define OFF_WT   (OFF_U + SZ_U)         // 62592 float4 wt[64]
#define SZ_WT    (TQ*N_*16)             // 1024
#define OFF_OY   (OFF_WT + SZ_WT)       // 63616 int2 oy[64]
#define SZ_OY    (TQ*N_*8)              // 512
#define OFF_OX   (OFF_OY + SZ_OY)       // 64128 ushort2 ox[64]
#define SZ_OX    (TQ*N_*4)              // 256
#define SMEM_BYTES (OFF_OX + SZ_OX)     // 64384 -> 3 blocks/SM

#define PROJ_SMEM (MP*C_*4*2)           // 40960
#define OUT_SMEM  (MB*NH_*C_*2)         // 65536

// device scratch
__device__ __half g_xt[B_ * HW_ * C_];               // channels-last fp16 x
__device__ float  g_wqT[C_ * C_];                    // wq transposed [k][c]
__device__ float  g_wvT[C_ * C_];                    // wv transposed [k][c]
__device__ __half g_t[(size_t)B_ * Q_ * NH_ * C_];   // t[b,q,h,k]
__device__ __half g_m[(size_t)B_ * Q_ * NH_ * C_];   // m[b,q,h,k]
__device__ float  g_u[(size_t)B_ * Q_ * NH_];        // u[b,q,h]

// ---------------------------------------------------------------------------
// Prologue A: transpose wq, wv [c][k] -> [k][c]
// ---------------------------------------------------------------------------
__global__ void transpose_w_kernel(const float* __restrict__ wq,
                                   const float* __restrict__ wv) {
    __shared__ float tile[32][33];
    const float* src = blockIdx.z == 0 ? wq : wv;
    float* dst = blockIdx.z == 0 ? g_wqT : g_wvT;
    int c0 = blockIdx.x * 32;
    int k0 = blockIdx.y * 32;
    int tx = threadIdx.x, ty = threadIdx.y;   // 32x8
    #pragma unroll
    for (int dy = 0; dy < 32; dy += 8)
        tile[ty + dy][tx] = src[(size_t)(c0 + ty + dy) * C_ + k0 + tx];
    __syncthreads();
    #pragma unroll
    for (int dy = 0; dy < 32; dy += 8)
        dst[(size_t)(k0 + ty + dy) * C_ + c0 + tx] = tile[tx][ty + dy];
}

// ---------------------------------------------------------------------------
// Prologue B: transpose x [B,C,HW] -> g_xt [B,HW,C] (fp16)
// ---------------------------------------------------------------------------
__global__ void transpose_x_kernel(const float* __restrict__ x) {
    __shared__ float tile[32][33];
    int b  = blockIdx.z;
    int p0 = blockIdx.x * 32;   // HW
    int c0 = blockIdx.y * 32;   // C
    int tx = threadIdx.x, ty = threadIdx.y;   // 32x8
    #pragma unroll
    for (int dy = 0; dy < 32; dy += 8) {
        int c = c0 + ty + dy;
        int p = p0 + tx;
        float v = 0.f;
        if (p < HW_) v = x[(size_t)(b * C_ + c) * HW_ + p];
        tile[ty + dy][tx] = v;
    }
    __syncthreads();
    #pragma unroll
    for (int dy = 0; dy < 32; dy += 8) {
        int p = p0 + ty + dy;
        int c = c0 + tx;
        if (p < HW_)
            g_xt[(size_t)(b * HW_ + p) * C_ + c] = __float2half_rn(tile[tx][ty + dy]);
    }
}

// ---------------------------------------------------------------------------
// Kernel P: projections. 512 threads, MP=20 queries, 2 i-groups of 10.
// ---------------------------------------------------------------------------
__global__ __launch_bounds__(512, 2)
void proj_kernel(const float* __restrict__ q,  const float* __restrict__ bq,
                 const float* __restrict__ wk, const float* __restrict__ bk) {
    extern __shared__ float psm[];
    float* qb = psm;                 // [MP][256]
    float* qp = psm + MP * C_;       // [MP][256]

    const int tid = threadIdx.x;
    const int b   = blockIdx.y;
    const int q0  = blockIdx.x * MP;
    const int lc  = tid & 255;       // channel / k lane
    const int ig  = tid >> 8;        // i-group: 0 or 1
    const int i0  = ig * (MP / 2);   // 10 queries per group

    for (int idx = tid; idx < MP * C_; idx += 512)
        qb[idx] = q[(size_t)(b * Q_ + q0 + idx / C_) * C_ + (idx % C_)];
    __syncthreads();

    // ---- qp phase: (c, i-group); coalesced wqT; 4 FMA per LDS.128 ----
    {
        float acc[MP / 2];
        #pragma unroll
        for (int i = 0; i < MP / 2; i++) acc[i] = 0.f;
        #pragma unroll 2
        for (int k4 = 0; k4 < C_ / 4; k4++) {
            const float* wp = g_wqT + (size_t)(k4 * 4) * C_ + lc;
            float w0 = __ldg(wp);
            float w1 = __ldg(wp + C_);
            float w2 = __ldg(wp + 2 * C_);
            float w3 = __ldg(wp + 3 * C_);
            #pragma unroll
            for (int i = 0; i < MP / 2; i++) {
                float4 qv = *(const float4*)(qb + (i0 + i) * C_ + k4 * 4);
                acc[i] += qv.x * w0 + qv.y * w1 + qv.z * w2 + qv.w * w3;
            }
        }
        float bb = __ldg(bq + lc);
        #pragma unroll
        for (int i = 0; i < MP / 2; i++) qp[(i0 + i) * C_ + lc] = acc[i] + bb;
    }
    __syncthreads();

    // ---- t phase: (k, i-group); coalesced wk; fp16 out ----
    {
        for (int h = 0; h < NH_; h++) {
            float acc[MP / 2];
            #pragma unroll
            for (int i = 0; i < MP / 2; i++) acc[i] = 0.f;
            #pragma unroll 2
            for (int d4 = 0; d4 < D_ / 4; d4++) {
                const float* wp = wk + (size_t)(h * D_ + d4 * 4) * C_ + lc;
                float w0 = __ldg(wp);
                float w1 = __ldg(wp + C_);
                float w2 = __ldg(wp + 2 * C_);
                float w3 = __ldg(wp + 3 * C_);
                #pragma unroll
                for (int i = 0; i < MP / 2; i++) {
                    float4 qv = *(const float4*)(qp + (i0 + i) * C_ + h * D_ + d4 * 4);
                    acc[i] += qv.x * w0 + qv.y * w1 + qv.z * w2 + qv.w * w3;
                }
            }
            #pragma unroll
            for (int i = 0; i < MP / 2; i++)
                g_t[((size_t)(b * Q_ + q0 + i0 + i) * NH_ + h) * C_ + lc] =
                    __float2half_rn(acc[i]);
        }
    }

    // ---- u phase ----
    if (tid < MP * NH_) {
        int i = tid / NH_, h = tid % NH_;
        float s = 0.f;
        #pragma unroll
        for (int dd = 0; dd < D_; dd++)
            s += qp[i * C_ + h * D_ + dd] * __ldg(bk + h * D_ + dd);
        g_u[(size_t)(b * Q_ + q0 + i) * NH_ + h] = s;
    }
}

// ---------------------------------------------------------------------------
// Kernel F: gather + scores + softmax + m (to global). TQ=4, 512 thr, 3/SM.
// ---------------------------------------------------------------------------
__global__ __launch_bounds__(512, 3)
void deform_attn_kernel(const float* __restrict__ ref) {
    extern __shared__ char smc[];
    __half*  A_sm  = (__half*)(smc + OFF_A);
    __half*  t_sm  = (__half*)(smc + OFF_T);
    float*   ps_sm = (float*)(smc + OFF_PS);
    float*   sc_sm = (float*)(smc + OFF_SC);
    float*   at_sm = (float*)(smc + OFF_AT);
    float*   u_sm  = (float*)(smc + OFF_U);
    float4*  wt_sm = (float4*)(smc + OFF_WT);
    int2*    oy_sm = (int2*)(smc + OFF_OY);
    ushort2* ox_sm = (ushort2*)(smc + OFF_OX);

    const int tid = threadIdx.x;
    const int b   = blockIdx.y;
    const int gq0 = blockIdx.x * TQ;

    // ---- phase 0: ref precompute (64 thr) + t/u load ----
    if (tid < TQ * N_) {
        int i  = tid >> 4, j = tid & 15;
        int rr = (gq0 + i) * N_ + j;
        int n  = rr / Q_;
        int qq = rr - n * Q_;
        float2 g = __ldg((const float2*)(ref + (size_t)((b * Q_ + qq) * N_ + n) * 2));
        float gx = ((g.x + 1.0f) * (float)W_ - 1.0f) * 0.5f;
        float gy = ((g.y + 1.0f) * (float)H_ - 1.0f) * 0.5f;
        float x0f = floorf(gx), y0f = floorf(gy);
        float fx = gx - x0f, fy = gy - y0f;
        int x0 = (int)x0f, y0 = (int)y0f;
        int x1 = x0 + 1,   y1 = y0 + 1;
        bool vx0 = (x0 >= 0) & (x0 < W_);
        bool vx1 = (x1 >= 0) & (x1 < W_);
        bool vy0 = (y0 >= 0) & (y0 < H_);
        bool vy1 = (y1 >= 0) & (y1 < H_);
        float4 w;
        w.x = (vx0 && vy0) ? (1.f - fx) * (1.f - fy) : 0.f;
        w.y = (vx1 && vy0) ? fx * (1.f - fy)         : 0.f;
        w.z = (vx0 && vy1) ? (1.f - fx) * fy         : 0.f;
        w.w = (vx1 && vy1) ? fx * fy                 : 0.f;
        int x0c = min(max(x0, 0), W_ - 1);
        int x1c = min(max(x1, 0), W_ - 1);
        int y0c = min(max(y0, 0), H_ - 1);
        int y1c = min(max(y1, 0), H_ - 1);
        wt_sm[tid] = w;
        oy_sm[tid] = make_int2(y0c * W_ * C_, y1c * W_ * C_);
        ox_sm[tid] = make_ushort2((unsigned short)(x0c * C_),
                                  (unsigned short)(x1c * C_));
    }
    {
        const uint4* ts = (const uint4*)(g_t + (size_t)(b * Q_ + gq0) * NH_ * C_);
        uint4* td = (uint4*)t_sm;
        td[tid] = __ldg(ts + tid);
        td[tid + 512] = __ldg(ts + tid + 512);
    }
    if (tid < TQ * NH_)
        u_sm[tid] = __ldg(g_u + (size_t)(b * Q_ + gq0) * NH_ + tid);
    __syncthreads();

    // ---- gather: thread owns k-pair; 16 rows each ----
    {
        const int k2 = tid & 127;
        const int rg = tid >> 7;
        const __half* xb = g_xt + (size_t)b * HW_ * C_;
        #pragma unroll 4
        for (int row = rg; row < TQ * N_; row += 4) {
            float4  w  = wt_sm[row];
            int2    oy = oy_sm[row];
            ushort2 ox = ox_sm[row];
            float2 v00 = __half22float2(__ldg((const __half2*)(xb + oy.x + ox.x) + k2));
            float2 v01 = __half22float2(__ldg((const __half2*)(xb + oy.x + ox.y) + k2));
            float2 v10 = __half22float2(__ldg((const __half2*)(xb + oy.y + ox.x) + k2));
            float2 v11 = __half22float2(__ldg((const __half2*)(xb + oy.y + ox.y) + k2));
            float rx = w.x * v00.x + w.y * v01.x + w.z * v10.x + w.w * v11.x;
            float ry = w.x * v00.y + w.y * v01.y + w.z * v10.y + w.w * v11.y;
            *(__half2*)(A_sm + row * AP2 + 2 * k2) = __floats2half2_rn(rx, ry);
        }
    }
    __syncthreads();

    // ---- scores: 2x2 tile, 4-way k-split. tid = (kh, i, jp, hp) ----
    {
        const int kh = tid >> 7;            // k quarter (64 k's)
        const int r  = tid & 127;
        const int i  = r >> 5;
        const int jp = (r >> 2) & 7;        // j = 2jp, 2jp+1
        const int hp = r & 3;               // h = 2hp, 2hp+1
        const uint4* a0 = (const uint4*)(A_sm + (i * N_ + 2 * jp) * AP2) + kh * 8;
        const uint4* a1 = (const uint4*)(A_sm + (i * N_ + 2 * jp + 1) * AP2) + kh * 8;
        const uint4* t0 = (const uint4*)(t_sm + (i * NH_ + 2 * hp) * C_) + kh * 8;
        const uint4* t1 = (const uint4*)(t_sm + (i * NH_ + 2 * hp + 1) * C_) + kh * 8;
        float acc00 = 0.f, acc01 = 0.f, acc10 = 0.f, acc11 = 0.f;
        #pragma unroll
        for (int c8 = 0; c8 < 8; c8++) {
            uint4 av0 = a0[c8], av1 = a1[c8], tv0 = t0[c8], tv1 = t1[c8];
            const __half2* ah0 = (const __half2*)&av0;
            const __half2* ah1 = (const __half2*)&av1;
            const __half2* th0 = (const __half2*)&tv0;
            const __half2* th1 = (const __half2*)&tv1;
            #pragma unroll
            for (int p = 0; p < 4; p++) {
                float2 f0 = __half22float2(ah0[p]);
                float2 f1 = __half22float2(ah1[p]);
                float2 g0 = __half22float2(th0[p]);
                float2 g1 = __half22float2(th1[p]);
                acc00 += f0.x * g0.x + f0.y * g0.y;
                acc01 += f0.x * g1.x + f0.y * g1.y;
                acc10 += f1.x * g0.x + f1.y * g0.y;
                acc11 += f1.x * g1.x + f1.y * g1.y;
            }
        }
        float* ps = ps_sm + kh * 512 + i * 128;
        ps[(2 * jp) * 8 + 2 * hp]         = acc00;
        ps[(2 * jp) * 8 + 2 * hp + 1]     = acc01;
        ps[(2 * jp + 1) * 8 + 2 * hp]     = acc10;
        ps[(2 * jp + 1) * 8 + 2 * hp + 1] = acc11;
    }
    __syncthreads();

    // ---- reduce partials -> sc ----
    {
        const int i = tid >> 7;
        const int j = (tid >> 3) & 15;
        const int h = tid & 7;
        const int idx = i * 128 + j * 8 + h;
        float s = ps_sm[idx] + ps_sm[512 + idx] + ps_sm[1024 + idx] + ps_sm[1536 + idx];
        const float scale = 0.17677669529663687f; // 1/sqrt(32)
        sc_sm[(i * NH_ + h) * N_ + j] = (s + u_sm[i * NH_ + h]) * scale;
    }
    __syncthreads();

    // ---- softmax over j per (i,h): 32 threads; attn transposed fp32 ----
    if (tid < TQ * NH_) {
        int i = tid >> 3, h = tid & 7;
        float s[N_];
        float mx = -1e30f;
        #pragma unroll
        for (int j = 0; j < N_; j++) {
            s[j] = sc_sm[(i * NH_ + h) * N_ + j];
            mx = fmaxf(mx, s[j]);
        }
        float sum = 0.f;
        #pragma unroll
        for (int j = 0; j < N_; j++) { s[j] = expf(s[j] - mx); sum += s[j]; }
        float inv = 1.f / sum;
        #pragma unroll
        for (int j = 0; j < N_; j++)
            at_sm[(i * N_ + j) * NH_ + h] = s[j] * inv;
    }
    __syncthreads();

    // ---- m[i][h][k] = sum_j attn*A : thread owns (k-pair, i); write global ----
    {
        const int k2 = tid & 127;
        const int i  = tid >> 7;
        float accx[NH_], accy[NH_];
        #pragma unroll
        for (int h = 0; h < NH_; h++) { accx[h] = 0.f; accy[h] = 0.f; }
        #pragma unroll
        for (int j = 0; j < N_; j++) {
            float2 a = __half22float2(*(const __half2*)(A_sm + (i * N_ + j) * AP2 + 2 * k2));
            float4 p0 = *(const float4*)(at_sm + (i * N_ + j) * NH_);
            float4 p1 = *(const float4*)(at_sm + (i * N_ + j) * NH_ + 4);
            accx[0] += a.x * p0.x; accy[0] += a.y * p0.x;
            accx[1] += a.x * p0.y; accy[1] += a.y * p0.y;
            accx[2] += a.x * p0.z; accy[2] += a.y * p0.z;
            accx[3] += a.x * p0.w; accy[3] += a.y * p0.w;
            accx[4] += a.x * p1.x; accy[4] += a.y * p1.x;
            accx[5] += a.x * p1.y; accy[5] += a.y * p1.y;
            accx[6] += a.x * p1.z; accy[6] += a.y * p1.z;
            accx[7] += a.x * p1.w; accy[7] += a.y * p1.w;
        }
        __half* mb = g_m + (size_t)(b * Q_ + gq0 + i) * NH_ * C_;
        #pragma unroll
        for (int h = 0; h < NH_; h++)
            *(__half2*)(mb + h * C_ + 2 * k2) = __floats2half2_rn(accx[h], accy[h]);
    }
}

// ---------------------------------------------------------------------------
// Kernel O: out[r][c] = sum_k m[r][h(c)][k] * wvT[k][c] + bv[c].
// MB=16 queries/block (flattened over b*Q), 512 threads.
// ---------------------------------------------------------------------------
__global__ __launch_bounds__(512, 2)
void out_kernel(const float* __restrict__ bv, float* __restrict__ out) {
    extern __shared__ char osm[];
    __half* m_sm = (__half*)osm;     // [MB][8][256]

    const int tid = threadIdx.x;
    const int r0  = blockIdx.x * MB;

    // load m: MB*8*256 halves = 4096 uint4
    {
        const uint4* ms = (const uint4*)(g_m + (size_t)r0 * NH_ * C_);
        uint4* md = (uint4*)m_sm;
        #pragma unroll
        for (int rep = 0; rep < (MB * NH_ * C_ / 8) / 512; rep++)
            md[tid + rep * 512] = __ldg(ms + tid + rep * 512);
    }
    __syncthreads();

    const int c  = tid & 255;
    const int ig = tid >> 8;            // 2 groups of 8 queries
    const int h  = c >> 5;
    float bb = __ldg(bv + c);
    float acc[MB / 2];
    #pragma unroll
    for (int ii = 0; ii < MB / 2; ii++) acc[ii] = bb;
    #pragma unroll 2
    for (int k4 = 0; k4 < C_ / 4; k4++) {
        const float* wp = g_wvT + (size_t)(k4 * 4) * C_ + c;
        float w0 = __ldg(wp);
        float w1 = __ldg(wp + C_);
        float w2 = __ldg(wp + 2 * C_);
        float w3 = __ldg(wp + 3 * C_);
        #pragma unroll
        for (int ii = 0; ii < MB / 2; ii++) {
            int i = ig * (MB / 2) + ii;
            const __half2* mp = (const __half2*)(m_sm + (i * NH_ + h) * C_ + k4 * 4);
            float2 m01 = __half22float2(mp[0]);
            float2 m23 = __half22float2(mp[1]);
            acc[ii] += m01.x * w0 + m01.y * w1 + m23.x * w2 + m23.y * w3;
        }
    }
    #pragma unroll
    for (int ii = 0; ii < MB / 2; ii++) {
        int i = ig * (MB / 2) + ii;
        out[(size_t)(r0 + i) * C_ + c] = acc[ii];
    }
}

// ---------------------------------------------------------------------------
extern "C" void kernel_launch(void* const* d_in, const int* in_sizes, int n_in,
                              void* d_out, int out_size) {
    const float* x   = (const float*)d_in[0];
    const float* q   = (const float*)d_in[1];
    const float* ref = (const float*)d_in[2];
    const float* wq  = (const float*)d_in[3];
    const float* bq  = (const float*)d_in[4];
    const float* wk  = (const float*)d_in[5];
    const float* bk  = (const float*)d_in[6];
    const float* wv  = (const float*)d_in[7];
    const float* bv  = (const float*)d_in[8];
    float* out = (float*)d_out;

    (void)in_sizes; (void)n_in; (void)out_size;

    transpose_w_kernel<<<dim3(C_ / 32, C_ / 32, 2), dim3(32, 8)>>>(wq, wv);

    dim3 tg((HW_ + 31) / 32, C_ / 32, B_);
    transpose_x_kernel<<<tg, dim3(32, 8)>>>(x);

    cudaFuncSetAttribute(proj_kernel,
                         cudaFuncAttributeMaxDynamicSharedMemorySize, PROJ_SMEM);
    proj_kernel<<<dim3(Q_ / MP, B_), 512, PROJ_SMEM>>>(q, bq, wk, bk);

    cudaFuncSetAttribute(deform_attn_kernel,
                         cudaFuncAttributeMaxDynamicSharedMemorySize, SMEM_BYTES);
    deform_attn_kernel<<<dim3(Q_ / TQ, B_), 512, SMEM_BYTES>>>(ref);

    cudaFuncSetAttribute(out_kernel,
                         cudaFuncAttributeMaxDynamicSharedMemorySize, OUT_SMEM);
    out_kernel<<<(B_ * Q_) / MB, 512, OUT_SMEM>>>(bv, out);
}